// round 8
// baseline (speedup 1.0000x reference)
#include <cuda_runtime.h>
#include <cuda_fp16.h>

#define N_  4
#define C_  128
#define HW_ 4096
#define W_  64

union Half4 {
    uint2   u;
    __half2 h[2];
};

// ---------------------------------------------------------------------------
// Single fused kernel. One block per (n, channel-quad); 1024 threads.
// Thread t handles 4 CONSECUTIVE positions k = 4t..4t+3 so all gmem traffic
// is 128-bit:
//   staging : 4x LDG.128 (one per channel row) -> reg transpose -> 2x STS.128
//   taps    : 8x LDG.128 (2 per grid row, all 4 rows needed for validity)
//   output  : 4x STG.128 (one per channel row)
// Smem: s[j] = half4(x[ch0..ch0+3][j])  -> one LDS.64 per corner serves 4 ch.
// out = w0*x[c] + w1*x[c+1] + w2*x[c+64] + w3*x[c+65],
// w = outer([1-fx, fx], [fx, fy]) * valid   (faithful to source)
// ---------------------------------------------------------------------------
__global__ __launch_bounds__(1024, 1)
void fused_kernel(const float* __restrict__ x,
                  const float* __restrict__ grid,
                  float* __restrict__ out) {
    __shared__ uint2 s[HW_];   // 32 KB: half4 per position

    const int tid = threadIdx.x;          // 0..1023
    const int n   = blockIdx.x >> 5;      // 0..3
    const int ch0 = (blockIdx.x & 31) * 4;

    const float4* r0 = (const float4*)(x + (size_t)(n * C_ + ch0 + 0) * HW_);
    const float4* r1 = (const float4*)(x + (size_t)(n * C_ + ch0 + 1) * HW_);
    const float4* r2 = (const float4*)(x + (size_t)(n * C_ + ch0 + 2) * HW_);
    const float4* r3 = (const float4*)(x + (size_t)(n * C_ + ch0 + 3) * HW_);

    // ---- staging loads: one float4 chunk (positions 4t..4t+3) per channel
    float4 v0 = __ldg(r0 + tid);
    float4 v1 = __ldg(r1 + tid);
    float4 v2 = __ldg(r2 + tid);
    float4 v3 = __ldg(r3 + tid);

    // ---- tap loads: grid[n'][4t..4t+3] for all 4 grids (validity = .all(0))
    const float4* g4 = (const float4*)grid;   // (N, HW*2/4) float4
    float4 G[4][2];
#pragma unroll
    for (int r = 0; r < 4; ++r) {
        G[r][0] = __ldg(g4 + r * (HW_ / 2) + 2 * tid);
        G[r][1] = __ldg(g4 + r * (HW_ / 2) + 2 * tid + 1);
    }

    // ---- stage as half4 quads: 4 consecutive quads -> 2x STS.128
    {
        Half4 q0, q1, q2, q3;
        q0.h[0] = __floats2half2_rn(v0.x, v1.x);  q0.h[1] = __floats2half2_rn(v2.x, v3.x);
        q1.h[0] = __floats2half2_rn(v0.y, v1.y);  q1.h[1] = __floats2half2_rn(v2.y, v3.y);
        q2.h[0] = __floats2half2_rn(v0.z, v1.z);  q2.h[1] = __floats2half2_rn(v2.z, v3.z);
        q3.h[0] = __floats2half2_rn(v0.w, v1.w);  q3.h[1] = __floats2half2_rn(v2.w, v3.w);
        uint4* sd = (uint4*)&s[4 * tid];
        sd[0] = make_uint4(q0.u.x, q0.u.y, q1.u.x, q1.u.y);
        sd[1] = make_uint4(q2.u.x, q2.u.y, q3.u.x, q3.u.y);
    }

    // ---- tap math (register-only; overlaps barrier wait)
    int   c0[4];
    float fx[4], fy[4];
#pragma unroll
    for (int p = 0; p < 4; ++p) {
        float2 gg[4];
#pragma unroll
        for (int r = 0; r < 4; ++r) {
            float4 h = G[r][p >> 1];
            gg[r] = (p & 1) ? make_float2(h.z, h.w) : make_float2(h.x, h.y);
        }
        bool valid = true;
#pragma unroll
        for (int r = 0; r < 4; ++r)
            valid = valid && (gg[r].x >= -0.001f) && (gg[r].x <= 63.001f)
                          && (gg[r].y >= -0.001f) && (gg[r].y <= 63.001f);
        float2 go = gg[n];
        float xx = fminf(fmaxf(go.x, 0.001f), 62.999f);
        float yy = fminf(fmaxf(go.y, 0.001f), 62.999f);
        float flx = floorf(xx);
        float fly = floorf(yy);
        c0[p] = (int)flx * W_ + (int)fly;
        fx[p] = valid ? (xx - flx) : 0.f;
        fy[p] = valid ? (yy - fly) : 0.f;
    }
    __syncthreads();

    // ---- gather + math: per position 4 corners (LDS.64), fp32 accumulate.
    // oc[ch] holds the 4 positions of channel ch -> one STG.128 each.
    float4 oc0, oc1, oc2, oc3;
    float* po0 = (float*)&oc0;
    float* po1 = (float*)&oc1;
    float* po2 = (float*)&oc2;
    float* po3 = (float*)&oc3;
#pragma unroll
    for (int p = 0; p < 4; ++p) {
        int c = c0[p];
        Half4 t0, t1, t2, t3;
        t0.u = s[c];
        t1.u = s[c + 1];
        t2.u = s[c + 64];
        t3.u = s[c + 65];

        float w0 = (1.f - fx[p]) * fx[p];
        float w1 = (1.f - fx[p]) * fy[p];
        float w2 = fx[p] * fx[p];
        float w3 = fx[p] * fy[p];

        float2 a01 = __half22float2(t0.h[0]), a23 = __half22float2(t0.h[1]);
        float2 b01 = __half22float2(t1.h[0]), b23 = __half22float2(t1.h[1]);
        float2 c01 = __half22float2(t2.h[0]), c23 = __half22float2(t2.h[1]);
        float2 d01 = __half22float2(t3.h[0]), d23 = __half22float2(t3.h[1]);

        po0[p] = w0 * a01.x + w1 * b01.x + w2 * c01.x + w3 * d01.x;
        po1[p] = w0 * a01.y + w1 * b01.y + w2 * c01.y + w3 * d01.y;
        po2[p] = w0 * a23.x + w1 * b23.x + w2 * c23.x + w3 * d23.x;
        po3[p] = w0 * a23.y + w1 * b23.y + w2 * c23.y + w3 * d23.y;
    }

    float4* ob = (float4*)(out + (size_t)(n * C_ + ch0) * HW_);
    const int q = HW_ / 4;   // 1024 float4 per channel row
    ob[0 * q + tid] = oc0;
    ob[1 * q + tid] = oc1;
    ob[2 * q + tid] = oc2;
    ob[3 * q + tid] = oc3;
}

extern "C" void kernel_launch(void* const* d_in, const int* in_sizes, int n_in,
                              void* d_out, int out_size) {
    const float* x    = (const float*)d_in[0];   // (4, 128, 4096) f32
    const float* grid = (const float*)d_in[1];   // (4, 64, 64, 2) f32
    float* out = (float*)d_out;                  // (4, 128, 4096) f32

    fused_kernel<<<N_ * (C_ / 4), 1024>>>(x, grid, out);
}